// round 14
// baseline (speedup 1.0000x reference)
#include <cuda_runtime.h>
#include <cstdint>

// Problem shape (fixed by the reference)
#define S 32768
#define H 1024
#define B1 148            // 1 CTA per SM (co-resident -> grid barrier safe)
#define TPB 384
#define WPB 12
#define NF4 (H / 4)
#define NWARPS (B1 * WPB) // 1776
#define SPLIT 28672       // rows [0, SPLIT) pinned in L2 (112 MB), rest streamed

__device__ float4 g_part[NF4][B1];
__device__ unsigned int g_cnt;   // monotone epoch counter (graph-replay safe)

// 256-bit eviction-hinted loads (sm_103a requires .v8.b32 with L2:: hints).
// Loads 8 consecutive floats (32B, must be 32B-aligned) into two float4s.
__device__ __forceinline__ void ldg8_keep(float4& a, float4& b, const float* p) {
    uint32_t r0, r1, r2, r3, r4, r5, r6, r7;
    asm volatile("ld.global.nc.L2::evict_last.v8.b32 {%0,%1,%2,%3,%4,%5,%6,%7}, [%8];"
                 : "=r"(r0), "=r"(r1), "=r"(r2), "=r"(r3),
                   "=r"(r4), "=r"(r5), "=r"(r6), "=r"(r7) : "l"(p));
    a.x = __uint_as_float(r0); a.y = __uint_as_float(r1);
    a.z = __uint_as_float(r2); a.w = __uint_as_float(r3);
    b.x = __uint_as_float(r4); b.y = __uint_as_float(r5);
    b.z = __uint_as_float(r6); b.w = __uint_as_float(r7);
}
__device__ __forceinline__ void ldg8_stream(float4& a, float4& b, const float* p) {
    uint32_t r0, r1, r2, r3, r4, r5, r6, r7;
    asm volatile("ld.global.nc.L2::evict_first.v8.b32 {%0,%1,%2,%3,%4,%5,%6,%7}, [%8];"
                 : "=r"(r0), "=r"(r1), "=r"(r2), "=r"(r3),
                   "=r"(r4), "=r"(r5), "=r"(r6), "=r"(r7) : "l"(p));
    a.x = __uint_as_float(r0); a.y = __uint_as_float(r1);
    a.z = __uint_as_float(r2); a.w = __uint_as_float(r3);
    b.x = __uint_as_float(r4); b.y = __uint_as_float(r5);
    b.z = __uint_as_float(r6); b.w = __uint_as_float(r7);
}

// Lane owns floats {c*256 + lane*8 .. +7} for c=0..3  -> kv[2c], kv[2c+1].
template <bool KEEP>
__device__ __forceinline__ void load_row(float4 kv[8], const float* __restrict__ keys,
                                         int row, int lane) {
    const float* base = keys + (size_t)row * H + lane * 8;
#pragma unroll
    for (int c = 0; c < 4; c++) {
        if (KEEP) ldg8_keep(kv[2 * c], kv[2 * c + 1], base + c * 256);
        else      ldg8_stream(kv[2 * c], kv[2 * c + 1], base + c * 256);
    }
}

__device__ __forceinline__ void process_row(const float4 kv[8], const float4* qs4,
                                            float qn_inv, int lane, float4 acc[8]) {
    float dot = 0.f, ss = 0.f;
#pragma unroll
    for (int c = 0; c < 4; c++) {
        const float4 qa = qs4[c * 64 + lane * 2];
        const float4 qb = qs4[c * 64 + lane * 2 + 1];
        const float4 ka = kv[2 * c], kb = kv[2 * c + 1];
        dot += qa.x * ka.x + qa.y * ka.y + qa.z * ka.z + qa.w * ka.w
             + qb.x * kb.x + qb.y * kb.y + qb.z * kb.z + qb.w * kb.w;
        ss  += ka.x * ka.x + ka.y * ka.y + ka.z * ka.z + ka.w * ka.w
             + kb.x * kb.x + kb.y * kb.y + kb.z * kb.z + kb.w * kb.w;
    }
#pragma unroll
    for (int o = 16; o > 0; o >>= 1) {
        dot += __shfl_xor_sync(0xffffffffu, dot, o);
        ss  += __shfl_xor_sync(0xffffffffu, ss, o);
    }
    const float cosv = dot * qn_inv * rsqrtf(ss);
#pragma unroll
    for (int j = 0; j < 8; j++) {
        acc[j].x += cosv * kv[j].x;
        acc[j].y += cosv * kv[j].y;
        acc[j].z += cosv * kv[j].z;
        acc[j].w += cosv * kv[j].w;
    }
}

__global__ __launch_bounds__(TPB, 1)
void cosattn_fused(const float* __restrict__ query,
                   const float* __restrict__ keys,
                   float* __restrict__ out) {
    __shared__ float q_s[H];             // 4 KB
    __shared__ float warp_ctx[WPB][H];   // 48 KB

    const int tid  = threadIdx.x;
    const int wid  = tid >> 5;
    const int lane = tid & 31;
    const int gwarp = blockIdx.x * WPB + wid;   // < 1776

    for (int i = tid; i < NF4; i += TPB)
        ((float4*)q_s)[i] = ((const float4*)query)[i];
    __syncthreads();

    const float4* qs4 = (const float4*)q_s;
    float qss = 0.f;
#pragma unroll
    for (int c = 0; c < 4; c++) {
        const float4 qa = qs4[c * 64 + lane * 2];
        const float4 qb = qs4[c * 64 + lane * 2 + 1];
        qss += qa.x * qa.x + qa.y * qa.y + qa.z * qa.z + qa.w * qa.w
             + qb.x * qb.x + qb.y * qb.y + qb.z * qb.z + qb.w * qb.w;
    }
#pragma unroll
    for (int o = 16; o > 0; o >>= 1)
        qss += __shfl_xor_sync(0xffffffffu, qss, o);
    const float qn_inv = rsqrtf(qss);

    float4 acc[8];
#pragma unroll
    for (int j = 0; j < 8; j++) acc[j] = make_float4(0.f, 0.f, 0.f, 0.f);

    // ---- Double-buffered main loop; pinned region uses evict_last loads ----
    float4 ka[8], kb[8];
    int next = gwarp + NWARPS;
    if (gwarp < SPLIT) load_row<true>(ka, keys, gwarp, lane);
    else               load_row<false>(ka, keys, gwarp, lane);
    for (;;) {
        if (next < S) {
            if (next < SPLIT) load_row<true>(kb, keys, next, lane);
            else              load_row<false>(kb, keys, next, lane);
        }
        process_row(ka, qs4, qn_inv, lane, acc);
        if (next >= S) break;
        next += NWARPS;

        if (next < S) {
            if (next < SPLIT) load_row<true>(ka, keys, next, lane);
            else              load_row<false>(ka, keys, next, lane);
        }
        process_row(kb, qs4, qn_inv, lane, acc);
        if (next >= S) break;
        next += NWARPS;
    }

    // Block-level reduce via smem (lane writes its owned columns).
    {
        float4* w4 = (float4*)warp_ctx[wid];
#pragma unroll
        for (int c = 0; c < 4; c++) {
            w4[c * 64 + lane * 2]     = acc[2 * c];
            w4[c * 64 + lane * 2 + 1] = acc[2 * c + 1];
        }
    }
    __syncthreads();

    if (tid < NF4) {
        float4 sum = make_float4(0.f, 0.f, 0.f, 0.f);
#pragma unroll
        for (int w = 0; w < WPB; w++) {
            float4 v = ((const float4*)warp_ctx[w])[tid];
            sum.x += v.x; sum.y += v.y; sum.z += v.z; sum.w += v.w;
        }
        g_part[tid][blockIdx.x] = sum;
    }

    // ---- Grid barrier (148 co-resident blocks) ----
    __threadfence();
    __syncthreads();
    if (tid == 0) {
        unsigned int old = atomicAdd(&g_cnt, 1u);
        unsigned int target = old - (old % B1) + B1;
        while (*(volatile unsigned int*)&g_cnt < target)
            __nanosleep(64);
    }
    __syncthreads();
    __threadfence();

    // ---- Phase 2: warp 0 -> column blockIdx.x, warp 1 -> column blockIdx.x + 148 ----
    {
        const int c = blockIdx.x + wid * B1;
        if (c < NF4 && wid < 2) {
            float4 a = make_float4(0.f, 0.f, 0.f, 0.f);
            for (int r = lane; r < B1; r += 32) {
                float4 v = g_part[c][r];
                a.x += v.x; a.y += v.y; a.z += v.z; a.w += v.w;
            }
#pragma unroll
            for (int o = 16; o > 0; o >>= 1) {
                a.x += __shfl_xor_sync(0xffffffffu, a.x, o);
                a.y += __shfl_xor_sync(0xffffffffu, a.y, o);
                a.z += __shfl_xor_sync(0xffffffffu, a.z, o);
                a.w += __shfl_xor_sync(0xffffffffu, a.w, o);
            }
            if (lane == 0)
                ((float4*)out)[c] = a;
        }
    }
}

extern "C" void kernel_launch(void* const* d_in, const int* in_sizes, int n_in,
                              void* d_out, int out_size) {
    const float* query = (const float*)d_in[0];  // [1, 1024]
    const float* keys  = (const float*)d_in[1];  // [32768, 1024]
    float* out = (float*)d_out;                  // [1, 1024]

    cosattn_fused<<<B1, TPB>>>(query, keys, out);
}